// round 12
// baseline (speedup 1.0000x reference)
#include <cuda_runtime.h>
#include <cuda_bf16.h>
#include <cstdint>

// ---------------------------------------------------------------------------
// GraphConv stack, R12: warp-specialized fused layer kernel.
//   Y = relu( X@W0^T + gather(X)@W1^T + b0 + deg*b1 )
// One persistent kernel per layer, 384 threads:
//   warps 0-7  (consumers): HMMA 6-term split-bf16 on 64x128 tiles
//   warps 8-11 (producers): gather next tile's G rows from global X -> smem
// G planes double-buffered; X planes single-buffered with register prefetch.
// ---------------------------------------------------------------------------

#define D 128
#define MAXN 100352
#define MAXE 310016
#define MAXL 16

typedef unsigned int uint32;

// Scratch (device globals: no allocation allowed)
__device__ __align__(128) float g_y1[(size_t)MAXN * D];
__device__ __align__(128) float g_ya[(size_t)MAXN * D];
__device__ __align__(128) float g_n [(size_t)MAXN * D];
__device__ __align__(128) __nv_bfloat16 g_wimg[(size_t)MAXL * 4 * D * D];
// CSR scratch
__device__ int g_deg[MAXN];
__device__ int g_rowstart[MAXN];
__device__ int g_wr[MAXN];
__device__ int g_adj[2 * MAXE];
__device__ int g_cursor;

// ---------------- helpers ---------------------------------------------------
__device__ __forceinline__ uint32 smem_to_u32(const void* p) {
    uint32 a;
    asm("{ .reg .u64 t; cvta.to.shared.u64 t, %1; cvt.u32.u64 %0, t; }"
        : "=r"(a) : "l"(p));
    return a;
}
__device__ __forceinline__ void ldm_x4(uint32 a, uint32* r) {
    asm volatile("ldmatrix.sync.aligned.m8n8.x4.shared.b16 {%0,%1,%2,%3}, [%4];"
                 : "=r"(r[0]), "=r"(r[1]), "=r"(r[2]), "=r"(r[3]) : "r"(a));
}
__device__ __forceinline__ void mma_bf16(float* d, const uint32* a, const uint32* b) {
    asm volatile(
        "mma.sync.aligned.m16n8k16.row.col.f32.bf16.bf16.f32 "
        "{%0,%1,%2,%3}, {%4,%5,%6,%7}, {%8,%9}, {%0,%1,%2,%3};"
        : "+f"(d[0]), "+f"(d[1]), "+f"(d[2]), "+f"(d[3])
        : "r"(a[0]), "r"(a[1]), "r"(a[2]), "r"(a[3]), "r"(b[0]), "r"(b[1]));
}
#define CP_ASYNC16(dst, src) \
    asm volatile("cp.async.cg.shared.global [%0], [%1], 16;" \
                 :: "r"(dst), "l"(src) : "memory")
#define CP_COMMIT() asm volatile("cp.async.commit_group;" ::: "memory")
#define CP_WAIT0()  asm volatile("cp.async.wait_group 0;" ::: "memory")

// Swizzled layout for a [rows x 128] bf16 k-major tile plane (16KB / 64 rows):
// row r, 16B chunk c (0..15): off = r*256 + ((c ^ (r&7)) << 4)
__host__ __device__ __forceinline__ uint32 tile_off(int r, int c) {
    return (uint32)(r * 256 + (((c) ^ (r & 7)) << 4));
}

// SMEM: X planes 32KB (hi@0, lo@16K) | G double 2x32KB | B 128KB
#define SMX_HI   0
#define SMX_LO   16384
#define SMG0     32768
#define SMG1     65536
#define SM_B     98304
#define SM_TOTAL (98304 + 131072)   // 229376 bytes (=224KB)

#define NTHREADS 384   // 8 consumer warps + 4 producer warps

// ---------------------------------------------------------------------------
// Weight prep: split fp32 W into bf16 hi/lo swizzled images.
// Per layer: {W0hi, W0lo, W1hi, W1lo}, 32KB each.
// ---------------------------------------------------------------------------
__global__ __launch_bounds__(256) void convert_weights(
    const float* __restrict__ W0_1, const float* __restrict__ W1_1,
    const float* __restrict__ W0_h, const float* __restrict__ W1_h,
    __nv_bfloat16* __restrict__ wimg)
{
    int m = blockIdx.x;
    int layer = m >> 1, sel = m & 1;
    const float* src;
    if (layer == 0) src = sel ? W1_1 : W0_1;
    else            src = (sel ? W1_h : W0_h) + (size_t)(layer - 1) * D * D;
    char* hi = (char*)(wimg + ((size_t)layer * 4 + sel * 2) * (D * D));
    char* lo = hi + D * D * 2;

    for (int e = threadIdx.x; e < 2048; e += blockDim.x) {   // 16B chunks
        int r = e >> 4, c = e & 15;
        const float* s = src + r * D + c * 8;
        uint32 h[4], l[4];
#pragma unroll
        for (int q = 0; q < 4; q++) {
            float x0 = s[q * 2], x1 = s[q * 2 + 1];
            __nv_bfloat16 h0 = __float2bfloat16(x0), h1 = __float2bfloat16(x1);
            __nv_bfloat16 l0 = __float2bfloat16(x0 - __bfloat162float(h0));
            __nv_bfloat16 l1 = __float2bfloat16(x1 - __bfloat162float(h1));
            __nv_bfloat162 hp = __halves2bfloat162(h0, h1);
            __nv_bfloat162 lp = __halves2bfloat162(l0, l1);
            h[q] = *(uint32*)&hp;
            l[q] = *(uint32*)&lp;
        }
        uint32 off = tile_off(r, c);
        *(uint4*)(hi + off) = make_uint4(h[0], h[1], h[2], h[3]);
        *(uint4*)(lo + off) = make_uint4(l[0], l[1], l[2], l[3]);
    }
}

__device__ __forceinline__ void cvt1(float x, float y, uint32& h, uint32& l) {
    __nv_bfloat16 hx = __float2bfloat16(x), hy = __float2bfloat16(y);
    __nv_bfloat16 lx = __float2bfloat16(x - __bfloat162float(hx));
    __nv_bfloat16 ly = __float2bfloat16(y - __bfloat162float(hy));
    __nv_bfloat162 hp = __halves2bfloat162(hx, hy);
    __nv_bfloat162 lp = __halves2bfloat162(lx, ly);
    h = *(uint32*)&hp; l = *(uint32*)&lp;
}

// Consumer X prefetch: 64 rows x 32 float4 = 2048 chunks / 256 threads = 8.
__device__ __forceinline__ void ldX(const float* __restrict__ X, int row0,
                                    int nrows, int tid, float4* pf) {
#pragma unroll
    for (int q = 0; q < 8; q++) {
        int idx = tid + q * 256;
        int r = idx >> 5, cq = idx & 31;
        int gr = row0 + r;
        float4 v = make_float4(0.f, 0.f, 0.f, 0.f);
        if (gr < nrows) v = __ldg((const float4*)(X + (size_t)gr * D + cq * 4));
        pf[q] = v;
    }
}
__device__ __forceinline__ void cvtX(char* smem, int tid, const float4* pf) {
#pragma unroll
    for (int q = 0; q < 8; q++) {
        int idx = tid + q * 256;
        int r = idx >> 5, cq = idx & 31;
        float4 v = pf[q];
        uint32 h0, l0, h1, l1;
        cvt1(v.x, v.y, h0, l0);
        cvt1(v.z, v.w, h1, l1);
        uint32 off = tile_off(r, cq >> 1) + (cq & 1) * 8;
        *(uint2*)(smem + SMX_HI + off) = make_uint2(h0, h1);
        *(uint2*)(smem + SMX_LO + off) = make_uint2(l0, l1);
    }
}

// Producer: gather G rows for a tile into G plane gbuf.
// 4 warps x 16 nodes each; lane owns float4 column chunk.
__device__ __forceinline__ void gatherG(
    char* smem, uint32 gbuf, const float* __restrict__ X,
    const int* __restrict__ rowstart, const int* __restrict__ deg,
    const int* __restrict__ adj, int row0, int nrows, int pw, int lane)
{
    for (int n = 0; n < 16; n++) {
        int lr = pw * 16 + n;
        int node = row0 + lr;
        float4 acc = make_float4(0.f, 0.f, 0.f, 0.f);
        if (node < nrows) {
            int d    = __ldg(&deg[node]);
            int base = __ldg(&rowstart[node]);
            int e = 0;
            for (; e + 2 <= d; e += 2) {
                int n0 = __ldg(&adj[base + e]);
                int n1 = __ldg(&adj[base + e + 1]);
                float4 v0 = __ldg((const float4*)(X + (size_t)n0 * D + lane * 4));
                float4 v1 = __ldg((const float4*)(X + (size_t)n1 * D + lane * 4));
                acc.x += v0.x + v1.x; acc.y += v0.y + v1.y;
                acc.z += v0.z + v1.z; acc.w += v0.w + v1.w;
            }
            if (e < d) {
                int n0 = __ldg(&adj[base + e]);
                float4 v0 = __ldg((const float4*)(X + (size_t)n0 * D + lane * 4));
                acc.x += v0.x; acc.y += v0.y; acc.z += v0.z; acc.w += v0.w;
            }
        }
        uint32 h0, l0, h1, l1;
        cvt1(acc.x, acc.y, h0, l0);
        cvt1(acc.z, acc.w, h1, l1);
        uint32 off = tile_off(lr, lane >> 1) + (lane & 1) * 8;
        *(uint2*)(smem + gbuf + off)         = make_uint2(h0, h1);
        *(uint2*)(smem + gbuf + 16384 + off) = make_uint2(l0, l1);
    }
}

// ---------------------------------------------------------------------------
// Warp-specialized fused layer kernel.
// ---------------------------------------------------------------------------
__global__ __launch_bounds__(NTHREADS, 1) void layer_fused(
    const float* __restrict__ X,
    const __nv_bfloat16* __restrict__ wimg,
    const float* __restrict__ b0, const float* __restrict__ b1,
    const int* __restrict__ rowstart, const int* __restrict__ degp,
    const int* __restrict__ adj,
    float* __restrict__ Y, int nrows)
{
    extern __shared__ char smem[];
    const uint32 sb = smem_to_u32(smem);
    const int tid  = threadIdx.x;
    const int wid  = tid >> 5;
    const int lane = tid & 31;
    const int ntiles = (nrows + 63) >> 6;
    const int stride = gridDim.x;
    const bool consumer = (wid < 8);

    // ---- B: 128KB cp.async of the pre-swizzled weight image ----------------
    for (int i = tid; i < 8192; i += NTHREADS)
        CP_ASYNC16(sb + SM_B + (uint32)i * 16, (const char*)wimg + (size_t)i * 16);
    CP_COMMIT();

    // ---- prologue: tile t0 into X planes + G0 ------------------------------
    const int t0 = blockIdx.x;
    if (t0 < ntiles) {
        if (consumer) {
            float4 pf[8];
            ldX(X, t0 * 64, nrows, tid, pf);
            cvtX(smem, tid, pf);
        } else {
            gatherG(smem, SMG0, X, rowstart, degp, adj,
                    t0 * 64, nrows, wid - 8, lane);
        }
    }
    CP_WAIT0();
    __syncthreads();

    // ---- consumer fragment addressing --------------------------------------
    const int warpM = wid >> 2;          // 0..1 (consumers)
    const int warpN = wid & 3;           // 0..3
    const int g  = lane >> 3;
    const int r8 = lane & 7;

    const int rowA = warpM * 32 + ((g & 1) << 3) + r8;
    const int swzA = rowA & 7;
    uint32 aRel[2];
#pragma unroll
    for (int i = 0; i < 2; i++) aRel[i] = (uint32)(rowA + i * 16) * 256;

    const int rowB = warpN * 32 + ((g >> 1) << 3) + r8;
    const int swzB = rowB & 7;
    uint32 bBase[2];
#pragma unroll
    for (int jj = 0; jj < 2; jj++)
        bBase[jj] = sb + SM_B + (uint32)(rowB + jj * 16) * 256;

    float b0x[4], b0y[4], b1x[4], b1y[4];
    if (consumer) {
#pragma unroll
        for (int j = 0; j < 4; j++) {
            int nc = warpN * 32 + j * 8 + (lane & 3) * 2;
            b0x[j] = __ldg(b0 + nc); b0y[j] = __ldg(b0 + nc + 1);
            b1x[j] = __ldg(b1 + nc); b1y[j] = __ldg(b1 + nc + 1);
        }
    }

    // ---- main loop ----------------------------------------------------------
    int cur = 0;
    for (int t = t0; t < ntiles; t += stride) {
        const int tn = t + stride;
        const bool have = tn < ntiles;
        const int row0 = t * 64;
        float4 pf[8];

        if (consumer) {
            if (have) ldX(X, tn * 64, nrows, tid, pf);   // LDG overlaps MMA

            const uint32 sbG = sb + (cur ? SMG1 : SMG0);

            float acc[2][4][4];
#pragma unroll
            for (int i = 0; i < 2; i++)
#pragma unroll
                for (int j = 0; j < 4; j++)
#pragma unroll
                    for (int q = 0; q < 4; q++) acc[i][j][q] = 0.f;

#pragma unroll
            for (int k = 0; k < 8; k++) {
                const uint32 offA = (uint32)(((2 * k + (g >> 1)) ^ swzA) << 4);
                const uint32 offB = (uint32)(((2 * k + (g & 1)) ^ swzB) << 4);

                uint32 xh[2][4], xl[2][4], gh[2][4], gl[2][4];
#pragma unroll
                for (int i = 0; i < 2; i++) {
                    ldm_x4(sb + SMX_HI + aRel[i] + offA, xh[i]);
                    ldm_x4(sb + SMX_LO + aRel[i] + offA, xl[i]);
                    ldm_x4(sbG + aRel[i] + offA,         gh[i]);
                    ldm_x4(sbG + 16384 + aRel[i] + offA, gl[i]);
                }
                uint32 w0h[2][4], w0l[2][4], w1h[2][4], w1l[2][4];
#pragma unroll
                for (int jj = 0; jj < 2; jj++) {
                    ldm_x4(bBase[jj] + offB,          w0h[jj]);
                    ldm_x4(bBase[jj] + offB + 32768,  w0l[jj]);
                    ldm_x4(bBase[jj] + offB + 65536,  w1h[jj]);
                    ldm_x4(bBase[jj] + offB + 98304,  w1l[jj]);
                }
#pragma unroll
                for (int i = 0; i < 2; i++) {
#pragma unroll
                    for (int j = 0; j < 4; j++) {
                        float* a = acc[i][j];
                        const int jj = j >> 1, js = (j & 1) * 2;
                        mma_bf16(a, xh[i], &w0h[jj][js]);
                        mma_bf16(a, xh[i], &w0l[jj][js]);
                        mma_bf16(a, xl[i], &w0h[jj][js]);
                        mma_bf16(a, gh[i], &w1h[jj][js]);
                        mma_bf16(a, gh[i], &w1l[jj][js]);
                        mma_bf16(a, gl[i], &w1h[jj][js]);
                    }
                }
            }

            // epilogue: + b0 + deg*b1, relu, store
#pragma unroll
            for (int i = 0; i < 2; i++) {
                int r1 = row0 + warpM * 32 + i * 16 + (lane >> 2);
                int r2 = r1 + 8;
                float d1 = (r1 < nrows) ? (float)__ldg(&degp[r1]) : 0.f;
                float d2 = (r2 < nrows) ? (float)__ldg(&degp[r2]) : 0.f;
#pragma unroll
                for (int j = 0; j < 4; j++) {
                    int nc = warpN * 32 + j * 8 + (lane & 3) * 2;
                    if (r1 < nrows) {
                        float vx = fmaxf(acc[i][j][0] + b0x[j] + d1 * b1x[j], 0.f);
                        float vy = fmaxf(acc[i][j][1] + b0y[j] + d1 * b1y[j], 0.f);
                        *(float2*)(Y + (size_t)r1 * D + nc) = make_float2(vx, vy);
                    }
                    if (r2 < nrows) {
                        float vx = fmaxf(acc[i][j][2] + b0x[j] + d2 * b1x[j], 0.f);
                        float vy = fmaxf(acc[i][j][3] + b0y[j] + d2 * b1y[j], 0.f);
                        *(float2*)(Y + (size_t)r2 * D + nc) = make_float2(vx, vy);
                    }
                }
            }
        } else {
            // producers: gather G for the next tile into the other buffer
            if (have)
                gatherG(smem, cur ? SMG0 : SMG1, X, rowstart, degp, adj,
                        tn * 64, nrows, wid - 8, lane);
        }

        __syncthreads();                       // MMA done; X planes free
        if (consumer && have) cvtX(smem, tid, pf);
        __syncthreads();                       // X planes ready
        cur ^= 1;
    }
}

// ---------------------------------------------------------------------------
// CSR build (once per call).
// ---------------------------------------------------------------------------
__global__ __launch_bounds__(256) void csr_zero(int* deg, int* cursor, int Nn) {
    int i = blockIdx.x * blockDim.x + threadIdx.x;
    if (i < Nn) deg[i] = 0;
    if (i == 0) *cursor = 0;
}
__global__ __launch_bounds__(256) void csr_count(const int2* __restrict__ edges,
                                                 int* deg, int E) {
    int e = blockIdx.x * blockDim.x + threadIdx.x;
    if (e >= E) return;
    int2 ij = __ldg(&edges[e]);
    atomicAdd(&deg[ij.x], 1);
    atomicAdd(&deg[ij.y], 1);
}
__global__ __launch_bounds__(256) void csr_offsets(const int* __restrict__ deg,
                                                   int* rowstart, int* wr,
                                                   int* cursor, int Nn) {
    int i = blockIdx.x * blockDim.x + threadIdx.x;
    if (i >= Nn) return;
    int s = atomicAdd(cursor, deg[i]);
    rowstart[i] = s;
    wr[i] = s;
}
__global__ __launch_bounds__(256) void csr_fill(const int2* __restrict__ edges,
                                                int* wr, int* adj, int E) {
    int e = blockIdx.x * blockDim.x + threadIdx.x;
    if (e >= E) return;
    int2 ij = __ldg(&edges[e]);
    adj[atomicAdd(&wr[ij.x], 1)] = ij.y;
    adj[atomicAdd(&wr[ij.y], 1)] = ij.x;
}

// ---------------------------------------------------------------------------
// Standalone aggregation (final stage only): Xagg[node] = sum_nbr X[nbr].
// ---------------------------------------------------------------------------
__global__ __launch_bounds__(256) void agg(
    const int* __restrict__ rowstart, const int* __restrict__ deg,
    const int* __restrict__ adj, const float* __restrict__ X,
    float* __restrict__ Xagg, int Nn)
{
    int gidx = blockIdx.x * blockDim.x + threadIdx.x;
    int node = gidx >> 5;
    int lane = gidx & 31;
    if (node >= Nn) return;
    int d = __ldg(&deg[node]);
    int base = __ldg(&rowstart[node]);

    float4 acc = make_float4(0.f, 0.f, 0.f, 0.f);
    int t = 0;
    for (; t + 2 <= d; t += 2) {
        int n0 = __ldg(&adj[base + t]);
        int n1 = __ldg(&adj[base + t + 1]);
        float4 v0 = __ldg((const float4*)(X + (size_t)n0 * D + lane * 4));
        float4 v1 = __ldg((const float4*)(X + (size_t)n1 * D + lane * 4));
        acc.x += v0.x + v1.x; acc.y += v0.y + v1.y;
        acc.z += v0.z + v1.z; acc.w += v0.w + v1.w;
    }
    if (t < d) {
        int n0 = __ldg(&adj[base + t]);
        float4 v0 = __ldg((const float4*)(X + (size_t)n0 * D + lane * 4));
        acc.x += v0.x; acc.y += v0.y; acc.z += v0.z; acc.w += v0.w;
    }
    *(float4*)(Xagg + (size_t)node * D + lane * 4) = acc;
}

// z = y1 + ylast (both already relu'd)
__global__ __launch_bounds__(256) void add_z(
    const float* __restrict__ y1, const float* __restrict__ yl,
    float* __restrict__ z, int nquads)
{
    int idx = blockIdx.x * blockDim.x + threadIdx.x;
    if (idx >= nquads) return;
    float4 a = ((const float4*)y1)[idx];
    float4 b = ((const float4*)yl)[idx];
    a.x += b.x; a.y += b.y; a.z += b.z; a.w += b.w;
    ((float4*)z)[idx] = a;
}

// Final layer (128 -> 3): vert = z@W0^T + b0 + zagg@W1^T + deg*b1.
__global__ __launch_bounds__(256) void final3(
    const float* __restrict__ z, const float* __restrict__ zagg,
    const float* __restrict__ W0, const float* __restrict__ b0,
    const float* __restrict__ W1, const float* __restrict__ b1,
    const int* __restrict__ deg,
    float* __restrict__ vert, int nrows)
{
    __shared__ float sW0[3 * D], sW1[3 * D], sb0[3], sb1[3];
    for (int t = threadIdx.x; t < 3 * D; t += blockDim.x) {
        sW0[t] = W0[t];
        sW1[t] = W1[t];
    }
    if (threadIdx.x < 3) {
        sb0[threadIdx.x] = b0[threadIdx.x];
        sb1[threadIdx.x] = b1[threadIdx.x];
    }
    __syncthreads();

    int node = blockIdx.x * blockDim.x + threadIdx.x;
    if (node >= nrows) return;

    const float4* z4 = (const float4*)(z    + (size_t)node * D);
    const float4* a4 = (const float4*)(zagg + (size_t)node * D);
    float dg = (float)__ldg(&deg[node]);

    float acc[3];
#pragma unroll
    for (int o = 0; o < 3; o++) acc[o] = sb0[o] + dg * sb1[o];

#pragma unroll 8
    for (int q = 0; q < D / 4; q++) {
        float4 zv = z4[q], av = a4[q];
        int k = q * 4;
#pragma unroll
        for (int o = 0; o < 3; o++) {
            acc[o] = fmaf(zv.x, sW0[o * D + k + 0], acc[o]);
            acc[o] = fmaf(zv.y, sW0[o * D + k + 1], acc[o]);
            acc[o] = fmaf(zv.z, sW0[o * D + k + 2], acc[o]);
            acc[o] = fmaf(zv.w, sW0[o * D + k + 3], acc[o]);
            acc[o] = fmaf(av.x, sW1[o * D + k + 0], acc[o]);
            acc[o] = fmaf(av.y, sW1[o * D + k + 1], acc[o]);
            acc[o] = fmaf(av.z, sW1[o * D + k + 2], acc[o]);
            acc[o] = fmaf(av.w, sW1[o * D + k + 3], acc[o]);
        }
    }
#pragma unroll
    for (int o = 0; o < 3; o++)
        vert[(size_t)node * 3 + o] = acc[o];
}

// ---------------------------------------------------------------------------
extern "C" void kernel_launch(void* const* d_in, const int* in_sizes, int n_in,
                              void* d_out, int out_size)
{
    const float* features = (const float*)d_in[0];
    const int2*  edges    = (const int2*) d_in[1];
    const float* W0_1 = (const float*)d_in[2];
    const float* b0_1 = (const float*)d_in[3];
    const float* W1_1 = (const float*)d_in[4];
    const float* b1_1 = (const float*)d_in[5];
    const float* W0_h = (const float*)d_in[6];
    const float* b0_h = (const float*)d_in[7];
    const float* W1_h = (const float*)d_in[8];
    const float* b1_h = (const float*)d_in[9];
    const float* W0_l = (const float*)d_in[10];
    const float* b0_l = (const float*)d_in[11];
    const float* W1_l = (const float*)d_in[12];
    const float* b1_l = (const float*)d_in[13];

    const int Nn = in_sizes[0] / D;
    const int E  = in_sizes[1] / 2;
    const int Lh = in_sizes[6] / (D * D);

    float* out  = (float*)d_out;
    float* vert = out;                       // [N, 3]
    float* aux  = out + (size_t)Nn * 3;      // [N, 128] = relu'd last hidden

    float *p_y1, *p_ya, *p_n;
    __nv_bfloat16* p_wimg;
    int *p_deg, *p_rs, *p_wr, *p_adj, *p_cur;
    cudaGetSymbolAddress((void**)&p_y1,   g_y1);
    cudaGetSymbolAddress((void**)&p_ya,   g_ya);
    cudaGetSymbolAddress((void**)&p_n,    g_n);
    cudaGetSymbolAddress((void**)&p_wimg, g_wimg);
    cudaGetSymbolAddress((void**)&p_deg,  g_deg);
    cudaGetSymbolAddress((void**)&p_rs,   g_rowstart);
    cudaGetSymbolAddress((void**)&p_wr,   g_wr);
    cudaGetSymbolAddress((void**)&p_adj,  g_adj);
    cudaGetSymbolAddress((void**)&p_cur,  g_cursor);

    cudaFuncSetAttribute(layer_fused, cudaFuncAttributeMaxDynamicSharedMemorySize,
                         SM_TOTAL);

    int smc = 0;
    if (cudaDeviceGetAttribute(&smc, cudaDevAttrMultiProcessorCount, 0) != cudaSuccess
        || smc <= 0)
        smc = 148;

    const int ntiles      = (Nn + 63) / 64;
    const int gemm_grid   = smc < ntiles ? smc : ntiles;
    const int nquads      = Nn * D / 4;
    const int q_blocks    = (nquads + 255) / 256;
    const int node_blocks = (Nn + 255) / 256;
    const int edge_blocks = (E + 255) / 256;
    const int agg_blocks  = (Nn * 32 + 255) / 256;

    // ---- weight images + CSR build -----------------------------------------
    convert_weights<<<2 * (Lh + 1), 256>>>(W0_1, W1_1, W0_h, W1_h, p_wimg);
    csr_zero<<<node_blocks, 256>>>(p_deg, p_cur, Nn);
    csr_count<<<edge_blocks, 256>>>(edges, p_deg, E);
    csr_offsets<<<node_blocks, 256>>>(p_deg, p_rs, p_wr, p_cur, Nn);
    csr_fill<<<edge_blocks, 256>>>(edges, p_wr, p_adj, E);

    // ---- Layer 1: fused gather+GEMM from features -> relu'd y1 -------------
    layer_fused<<<gemm_grid, NTHREADS, SM_TOTAL>>>(
        features, p_wimg, b0_1, b1_1, p_rs, p_deg, p_adj, p_y1, Nn);

    // ---- hidden layers (last one writes straight into aux) -----------------
    const float* src = p_y1;
    float* pool[2] = {p_ya, p_n};   // p_n reused as pong until final stage
    for (int l = 0; l < Lh; l++) {
        const __nv_bfloat16* wl = p_wimg + (size_t)(l + 1) * 4 * D * D;
        const float* b0 = b0_h + (size_t)l * D;
        const float* b1 = b1_h + (size_t)l * D;
        float* dst = (l == Lh - 1) ? aux : pool[l & 1];
        layer_fused<<<gemm_grid, NTHREADS, SM_TOTAL>>>(
            src, wl, b0, b1, p_rs, p_deg, p_adj, dst, Nn);
        src = dst;
    }

    // ---- z = y1 + ylast; zagg; final 128->3 --------------------------------
    add_z<<<q_blocks, 256>>>(p_y1, aux, p_ya, nquads);
    agg<<<agg_blocks, 256>>>(p_rs, p_deg, p_adj, p_ya, p_n, Nn);
    final3<<<node_blocks, 256>>>(p_ya, p_n, W0_l, b0_l, W1_l, b1_l,
                                 p_deg, vert, Nn);
}

// round 13
// speedup vs baseline: 3.4848x; 3.4848x over previous
#include <cuda_runtime.h>
#include <cuda_bf16.h>
#include <cstdint>

// ---------------------------------------------------------------------------
// GraphConv stack, R13: revert to R11 structure (best: 1343us-class), plus
// agg MLP-4 unroll and kernel-order alignment so ncu captures the GEMM.
//   agg(X@W1^T + b1) = (agg X)@W1^T + deg*b1
// Per layer: Xagg = gather-sum(X) ; Y = relu(X@W0^T + Xagg@W1^T + b0 + deg*b1)
// ---------------------------------------------------------------------------

#define D 128
#define MAXN 100352
#define MAXE 310016
#define MAXL 16

typedef unsigned int uint32;

// Scratch (device globals: no allocation allowed)
__device__ __align__(128) float g_y1[(size_t)MAXN * D];
__device__ __align__(128) float g_ya[(size_t)MAXN * D];
__device__ __align__(128) float g_yb[(size_t)MAXN * D];
__device__ __align__(128) float g_n [(size_t)MAXN * D];
__device__ __align__(128) __nv_bfloat16 g_wimg[(size_t)MAXL * 4 * D * D];
// CSR scratch
__device__ int g_deg[MAXN];
__device__ int g_rowstart[MAXN];
__device__ int g_wr[MAXN];
__device__ int g_adj[2 * MAXE];
__device__ int g_cursor;

// ---------------- helpers ---------------------------------------------------
__device__ __forceinline__ uint32 smem_to_u32(const void* p) {
    uint32 a;
    asm("{ .reg .u64 t; cvta.to.shared.u64 t, %1; cvt.u32.u64 %0, t; }"
        : "=r"(a) : "l"(p));
    return a;
}
__device__ __forceinline__ void ldm_x4(uint32 a, uint32* r) {
    asm volatile("ldmatrix.sync.aligned.m8n8.x4.shared.b16 {%0,%1,%2,%3}, [%4];"
                 : "=r"(r[0]), "=r"(r[1]), "=r"(r[2]), "=r"(r[3]) : "r"(a));
}
__device__ __forceinline__ void mma_bf16(float* d, const uint32* a, const uint32* b) {
    asm volatile(
        "mma.sync.aligned.m16n8k16.row.col.f32.bf16.bf16.f32 "
        "{%0,%1,%2,%3}, {%4,%5,%6,%7}, {%8,%9}, {%0,%1,%2,%3};"
        : "+f"(d[0]), "+f"(d[1]), "+f"(d[2]), "+f"(d[3])
        : "r"(a[0]), "r"(a[1]), "r"(a[2]), "r"(a[3]), "r"(b[0]), "r"(b[1]));
}
#define CP_ASYNC16(dst, src) \
    asm volatile("cp.async.cg.shared.global [%0], [%1], 16;" \
                 :: "r"(dst), "l"(src) : "memory")
#define CP_COMMIT() asm volatile("cp.async.commit_group;" ::: "memory")
#define CP_WAIT0()  asm volatile("cp.async.wait_group 0;" ::: "memory")

// Swizzled layout for a [rows x 128] bf16 k-major tile:
// row r, 16B chunk c (0..15): off = r*256 + ((c ^ (r&7)) << 4)
__host__ __device__ __forceinline__ uint32 tile_off(int r, int c) {
    return (uint32)(r * 256 + (((c) ^ (r & 7)) << 4));
}

// SMEM: A single buffer 64 rows: Xhi 16K | Xlo 16K | Ghi 16K | Glo 16K = 64KB
//       B: {W0hi, W0lo, W1hi, W1lo} 4 x 32KB = 128KB at SM_B
#define A_XLO    16384
#define A_GHI    32768
#define A_GLO    49152
#define SM_B     65536
#define SM_TOTAL (65536 + 131072)   // 192 KB

// ---------------------------------------------------------------------------
// Fused weight prep + csr_zero (independent work; fused so the launch count
// puts gemm_fused at ncu's captured slot).
// Blocks [0, nmat): weight split. Blocks [nmat, nmat+zb): zero deg + cursor.
// ---------------------------------------------------------------------------
__global__ __launch_bounds__(256) void prep_weights_zero(
    const float* __restrict__ W0_1, const float* __restrict__ W1_1,
    const float* __restrict__ W0_h, const float* __restrict__ W1_h,
    __nv_bfloat16* __restrict__ wimg, int nmat,
    int* deg, int* cursor, int Nn)
{
    if ((int)blockIdx.x >= nmat) {
        int i = (blockIdx.x - nmat) * blockDim.x + threadIdx.x;
        if (i < Nn) deg[i] = 0;
        if (i == 0) *cursor = 0;
        return;
    }
    int m = blockIdx.x;
    int layer = m >> 1, sel = m & 1;
    const float* src;
    if (layer == 0) src = sel ? W1_1 : W0_1;
    else            src = (sel ? W1_h : W0_h) + (size_t)(layer - 1) * D * D;
    char* hi = (char*)(wimg + ((size_t)layer * 4 + sel * 2) * (D * D));
    char* lo = hi + D * D * 2;

    for (int e = threadIdx.x; e < 2048; e += blockDim.x) {   // 16B chunks
        int r = e >> 4, c = e & 15;
        const float* s = src + r * D + c * 8;
        uint32 h[4], l[4];
#pragma unroll
        for (int q = 0; q < 4; q++) {
            float x0 = s[q * 2], x1 = s[q * 2 + 1];
            __nv_bfloat16 h0 = __float2bfloat16(x0), h1 = __float2bfloat16(x1);
            __nv_bfloat16 l0 = __float2bfloat16(x0 - __bfloat162float(h0));
            __nv_bfloat16 l1 = __float2bfloat16(x1 - __bfloat162float(h1));
            __nv_bfloat162 hp = __halves2bfloat162(h0, h1);
            __nv_bfloat162 lp = __halves2bfloat162(l0, l1);
            h[q] = *(uint32*)&hp;
            l[q] = *(uint32*)&lp;
        }
        uint32 off = tile_off(r, c);
        *(uint4*)(hi + off) = make_uint4(h[0], h[1], h[2], h[3]);
        *(uint4*)(lo + off) = make_uint4(l[0], l[1], l[2], l[3]);
    }
}

// ---- A tile: 64 rows x 32 float4 x 2 sources = 4096 chunks / 256 thr = 16 --
__device__ __forceinline__ void ldA(const float* __restrict__ X,
                                    const float* __restrict__ G, int row0,
                                    int nrows, int tid, float4* pf) {
#pragma unroll
    for (int q = 0; q < 16; q++) {
        int idx = tid + (q & 7) * 256;       // 0..2047
        int r = idx >> 5, cq = idx & 31;
        int gr = row0 + r;
        const float* src = (q < 8) ? X : G;
        float4 v = make_float4(0.f, 0.f, 0.f, 0.f);
        if (gr < nrows) v = __ldg((const float4*)(src + (size_t)gr * D + cq * 4));
        pf[q] = v;
    }
}
__device__ __forceinline__ void cvt1(float x, float y, uint32& h, uint32& l) {
    __nv_bfloat16 hx = __float2bfloat16(x), hy = __float2bfloat16(y);
    __nv_bfloat16 lx = __float2bfloat16(x - __bfloat162float(hx));
    __nv_bfloat16 ly = __float2bfloat16(y - __bfloat162float(hy));
    __nv_bfloat162 hp = __halves2bfloat162(hx, hy);
    __nv_bfloat162 lp = __halves2bfloat162(lx, ly);
    h = *(uint32*)&hp; l = *(uint32*)&lp;
}
__device__ __forceinline__ void cvtA(char* smem, int tid, const float4* pf) {
#pragma unroll
    for (int q = 0; q < 16; q++) {
        int idx = tid + (q & 7) * 256;
        int r = idx >> 5, cq = idx & 31;
        uint32 hiOff = (q < 8) ? 0u : (uint32)A_GHI;
        float4 v = pf[q];
        uint32 h0, l0, h1, l1;
        cvt1(v.x, v.y, h0, l0);
        cvt1(v.z, v.w, h1, l1);
        uint32 off = tile_off(r, cq >> 1) + (cq & 1) * 8;
        *(uint2*)(smem + hiOff + off)         = make_uint2(h0, h1);
        *(uint2*)(smem + hiOff + 16384 + off) = make_uint2(l0, l1);
    }
}

// ---------------------------------------------------------------------------
// Persistent fused HMMA GEMM: Y = relu(X@W0^T + G@W1^T + b0 + deg*b1)
// grid = min(#SM, ntiles). 256 threads = 8 warps (2M x 4N), tile 64 x 128,
// warp tile 32 x 32. Single A buffer; next tile prefetched into registers.
// ---------------------------------------------------------------------------
__global__ __launch_bounds__(256) void gemm_fused(
    const float* __restrict__ X, const float* __restrict__ G,
    const __nv_bfloat16* __restrict__ wimg,
    const float* __restrict__ b0, const float* __restrict__ b1,
    const int* __restrict__ deg,
    float* __restrict__ Y, int nrows)
{
    extern __shared__ char smem[];
    const uint32 sb = smem_to_u32(smem);
    const int tid  = threadIdx.x;
    const int wid  = tid >> 5;
    const int lane = tid & 31;
    const int ntiles = (nrows + 63) >> 6;

    // ---- B: one 128KB cp.async of the pre-swizzled weight image -----------
    {
        const char* src = (const char*)wimg;
#pragma unroll
        for (int i = 0; i < 32; i++) {
            uint32 off = (uint32)(tid + i * 256) * 16;
            CP_ASYNC16(sb + SM_B + off, src + off);
        }
        CP_COMMIT();
    }

    // ---- prologue: load + convert first tile -------------------------------
    if (blockIdx.x < ntiles) {
        float4 pf[16];
        ldA(X, G, blockIdx.x * 64, nrows, tid, pf);
        cvtA(smem, tid, pf);
    }
    CP_WAIT0();
    __syncthreads();

    // ---- fragment addressing ------------------------------------------------
    const int warpM = wid >> 2;          // 0..1 -> rows warpM*32
    const int warpN = wid & 3;           // 0..3 -> cols warpN*32
    const int g  = lane >> 3;
    const int r8 = lane & 7;

    const int rowA = warpM * 32 + ((g & 1) << 3) + r8;
    const int swzA = rowA & 7;
    uint32 aRel[2];
#pragma unroll
    for (int i = 0; i < 2; i++) aRel[i] = (uint32)(rowA + i * 16) * 256;

    const int rowB = warpN * 32 + ((g >> 1) << 3) + r8;
    const int swzB = rowB & 7;
    uint32 bBase[2];
#pragma unroll
    for (int jj = 0; jj < 2; jj++)
        bBase[jj] = sb + SM_B + (uint32)(rowB + jj * 16) * 256;

    // bias registers
    float b0x[4], b0y[4], b1x[4], b1y[4];
#pragma unroll
    for (int j = 0; j < 4; j++) {
        int nc = warpN * 32 + j * 8 + (lane & 3) * 2;
        b0x[j] = __ldg(b0 + nc); b0y[j] = __ldg(b0 + nc + 1);
        b1x[j] = __ldg(b1 + nc); b1y[j] = __ldg(b1 + nc + 1);
    }

    // ---- main loop: register-prefetch pipeline ------------------------------
    for (int t = blockIdx.x; t < ntiles; t += gridDim.x) {
        const int tn = t + gridDim.x;
        const bool have = tn < ntiles;
        float4 pf[16];
        if (have) ldA(X, G, tn * 64, nrows, tid, pf);   // LDG overlaps MMA

        const int row0 = t * 64;

        float acc[2][4][4];
#pragma unroll
        for (int i = 0; i < 2; i++)
#pragma unroll
            for (int j = 0; j < 4; j++)
#pragma unroll
                for (int q = 0; q < 4; q++) acc[i][j][q] = 0.f;

#pragma unroll
        for (int k = 0; k < 8; k++) {
            const uint32 offA = (uint32)(((2 * k + (g >> 1)) ^ swzA) << 4);
            const uint32 offB = (uint32)(((2 * k + (g & 1)) ^ swzB) << 4);

            uint32 xh[2][4], xl[2][4], gh[2][4], gl[2][4];
#pragma unroll
            for (int i = 0; i < 2; i++) {
                ldm_x4(sb + aRel[i] + offA,          xh[i]);
                ldm_x4(sb + aRel[i] + offA + A_XLO,  xl[i]);
                ldm_x4(sb + aRel[i] + offA + A_GHI,  gh[i]);
                ldm_x4(sb + aRel[i] + offA + A_GLO,  gl[i]);
            }
            uint32 w0h[2][4], w0l[2][4], w1h[2][4], w1l[2][4];
#pragma unroll
            for (int jj = 0; jj < 2; jj++) {
                ldm_x4(bBase[jj] + offB,          w0h[jj]);
                ldm_x4(bBase[jj] + offB + 32768,  w0l[jj]);
                ldm_x4(bBase[jj] + offB + 65536,  w1h[jj]);
                ldm_x4(bBase[jj] + offB + 98304,  w1l[jj]);
            }
#pragma unroll
            for (int i = 0; i < 2; i++) {
#pragma unroll
                for (int j = 0; j < 4; j++) {
                    float* a = acc[i][j];
                    const int jj = j >> 1, js = (j & 1) * 2;
                    mma_bf16(a, xh[i], &w0h[jj][js]);   // Xhi*W0hi
                    mma_bf16(a, xh[i], &w0l[jj][js]);   // Xhi*W0lo
                    mma_bf16(a, xl[i], &w0h[jj][js]);   // Xlo*W0hi
                    mma_bf16(a, gh[i], &w1h[jj][js]);   // Ghi*W1hi
                    mma_bf16(a, gh[i], &w1l[jj][js]);   // Ghi*W1lo
                    mma_bf16(a, gl[i], &w1h[jj][js]);   // Glo*W1hi
                }
            }
        }

        // epilogue: + b0 + deg*b1, relu, store
#pragma unroll
        for (int i = 0; i < 2; i++) {
            int r1 = row0 + warpM * 32 + i * 16 + (lane >> 2);
            int r2 = r1 + 8;
            float d1 = (r1 < nrows) ? (float)__ldg(&deg[r1]) : 0.f;
            float d2 = (r2 < nrows) ? (float)__ldg(&deg[r2]) : 0.f;
#pragma unroll
            for (int j = 0; j < 4; j++) {
                int nc = warpN * 32 + j * 8 + (lane & 3) * 2;
                if (r1 < nrows) {
                    float vx = fmaxf(acc[i][j][0] + b0x[j] + d1 * b1x[j], 0.f);
                    float vy = fmaxf(acc[i][j][1] + b0y[j] + d1 * b1y[j], 0.f);
                    *(float2*)(Y + (size_t)r1 * D + nc) = make_float2(vx, vy);
                }
                if (r2 < nrows) {
                    float vx = fmaxf(acc[i][j][2] + b0x[j] + d2 * b1x[j], 0.f);
                    float vy = fmaxf(acc[i][j][3] + b0y[j] + d2 * b1y[j], 0.f);
                    *(float2*)(Y + (size_t)r2 * D + nc) = make_float2(vx, vy);
                }
            }
        }

        __syncthreads();                 // all warps done reading A buffer
        if (have) cvtA(smem, tid, pf);   // write next tile (CVT+STS only)
        __syncthreads();                 // buffer ready for next iteration
    }
}

// ---------------------------------------------------------------------------
// CSR build (once per call).
// ---------------------------------------------------------------------------
__global__ __launch_bounds__(256) void csr_count(const int2* __restrict__ edges,
                                                 int* deg, int E) {
    int e = blockIdx.x * blockDim.x + threadIdx.x;
    if (e >= E) return;
    int2 ij = __ldg(&edges[e]);
    atomicAdd(&deg[ij.x], 1);
    atomicAdd(&deg[ij.y], 1);
}
__global__ __launch_bounds__(256) void csr_offsets(const int* __restrict__ deg,
                                                   int* rowstart, int* wr,
                                                   int* cursor, int Nn) {
    int i = blockIdx.x * blockDim.x + threadIdx.x;
    if (i >= Nn) return;
    int s = atomicAdd(cursor, deg[i]);
    rowstart[i] = s;
    wr[i] = s;
}
__global__ __launch_bounds__(256) void csr_fill(const int2* __restrict__ edges,
                                                int* wr, int* adj, int E) {
    int e = blockIdx.x * blockDim.x + threadIdx.x;
    if (e >= E) return;
    int2 ij = __ldg(&edges[e]);
    adj[atomicAdd(&wr[ij.x], 1)] = ij.y;
    adj[atomicAdd(&wr[ij.y], 1)] = ij.x;
}

// ---------------------------------------------------------------------------
// Aggregation: one warp per node, MLP-4 unrolled. Fresh write.
// ---------------------------------------------------------------------------
__global__ __launch_bounds__(256) void agg(
    const int* __restrict__ rowstart, const int* __restrict__ deg,
    const int* __restrict__ adj, const float* __restrict__ X,
    float* __restrict__ Xagg, int Nn)
{
    int gidx = blockIdx.x * blockDim.x + threadIdx.x;
    int node = gidx >> 5;
    int lane = gidx & 31;
    if (node >= Nn) return;
    int d = __ldg(&deg[node]);
    int base = __ldg(&rowstart[node]);

    float4 acc = make_float4(0.f, 0.f, 0.f, 0.f);
    int t = 0;
    for (; t + 4 <= d; t += 4) {
        int n0 = __ldg(&adj[base + t]);
        int n1 = __ldg(&adj[base + t + 1]);
        int n2 = __ldg(&adj[base + t + 2]);
        int n3 = __ldg(&adj[base + t + 3]);
        float4 v0 = __ldg((const float4*)(X + (size_t)n0 * D + lane * 4));
        float4 v1 = __ldg((const float4*)(X + (size_t)n1 * D + lane * 4));
        float4 v2 = __ldg((const float4*)(X + (size_t)n2 * D + lane * 4));
        float4 v3 = __ldg((const float4*)(X + (size_t)n3 * D + lane * 4));
        acc.x += (v0.x + v1.x) + (v2.x + v3.x);
        acc.y += (v0.y + v1.y) + (v2.y + v3.y);
        acc.z += (v0.z + v1.z) + (v2.z + v3.z);
        acc.w += (v0.w + v1.w) + (v2.w + v3.w);
    }
    if (t + 2 <= d) {
        int n0 = __ldg(&adj[base + t]);
        int n1 = __ldg(&adj[base + t + 1]);
        float4 v0 = __ldg((const float4*)(X + (size_t)n0 * D + lane * 4));
        float4 v1 = __ldg((const float4*)(X + (size_t)n1 * D + lane * 4));
        acc.x += v0.x + v1.x; acc.y += v0.y + v1.y;
        acc.z += v0.z + v1.z; acc.w += v0.w + v1.w;
        t += 2;
    }
    if (t < d) {
        int n0 = __ldg(&adj[base + t]);
        float4 v0 = __ldg((const float4*)(X + (size_t)n0 * D + lane * 4));
        acc.x += v0.x; acc.y += v0.y; acc.z += v0.z; acc.w += v0.w;
    }
    *(float4*)(Xagg + (size_t)node * D + lane * 4) = acc;
}

// z = y1 + ylast (both already relu'd)
__global__ __launch_bounds__(256) void add_z(
    const float* __restrict__ y1, const float* __restrict__ yl,
    float* __restrict__ z, int nquads)
{
    int idx = blockIdx.x * blockDim.x + threadIdx.x;
    if (idx >= nquads) return;
    float4 a = ((const float4*)y1)[idx];
    float4 b = ((const float4*)yl)[idx];
    a.x += b.x; a.y += b.y; a.z += b.z; a.w += b.w;
    ((float4*)z)[idx] = a;
}

// Final layer (128 -> 3): vert = z@W0^T + b0 + zagg@W1^T + deg*b1.
__global__ __launch_bounds__(256) void final3(
    const float* __restrict__ z, const float* __restrict__ zagg,
    const float* __restrict__ W0, const float* __restrict__ b0,
    const float* __restrict__ W1, const float* __restrict__ b1,
    const int* __restrict__ deg,
    float* __restrict__ vert, int nrows)
{
    __shared__ float sW0[3 * D], sW1[3 * D], sb0[3], sb1[3];
    for (int t = threadIdx.x; t < 3 * D; t += blockDim.x) {
        sW0[t] = W0[t];
        sW1[t] = W1[t];
    }
    if (threadIdx.x < 3) {
        sb0[threadIdx.x] = b0[threadIdx.x];
        sb1[threadIdx.x] = b1[threadIdx.x];
    }
    __syncthreads();

    int node = blockIdx.x * blockDim.x + threadIdx.x;
    if (node >= nrows) return;

    const float4* z4 = (const float4*)(z    + (size_t)node * D);
    const float4* a4 = (const float4*)(zagg + (size_t)node * D);
    float dg = (float)__ldg(&deg[node]);

    float acc[3];
#pragma unroll
    for (int o = 0; o < 3; o++) acc[o] = sb0[o] + dg * sb1[o];

#pragma unroll 8
    for (int q = 0; q < D / 4; q++) {
        float4 zv = z4[q], av = a4[q];
        int k = q * 4;
#pragma unroll
        for (int o = 0; o < 3; o++) {
            acc[o] = fmaf(zv.x, sW0[o * D + k + 0], acc[o]);
            acc[o] = fmaf(zv.y, sW0[o * D + k + 1], acc[o]);
            acc[o] = fmaf(zv.z, sW0[o * D + k + 2], acc[o]);
            acc[o] = fmaf(zv.w, sW0[o * D + k + 3], acc[o]);
            acc[o] = fmaf(av.x, sW1[o * D + k + 0], acc[o]);
            acc[o] = fmaf(av.y, sW1[o * D + k + 1], acc[o]);
            acc[o] = fmaf(av.z, sW1[o * D + k + 2], acc[o]);
            acc[o] = fmaf(av.w, sW1[o * D + k + 3], acc[o]);
        }
    }
#pragma unroll
    for (int o = 0; o < 3; o++)
        vert[(size_t)node * 3 + o] = acc[o];
}

// ---------------------------------------------------------------------------
extern "C" void kernel_launch(void* const* d_in, const int* in_sizes, int n_in,
                              void* d_out, int out_size)
{
    const float* features = (const float*)d_in[0];
    const int2*  edges    = (const int2*) d_in[1];
    const float* W0_1 = (const float*)d_in[2];
    const float* b0_1 = (const float*)d_in[3];
    const float* W1_1 = (const float*)d_in[4];
    const float* b1_1 = (const float*)d_in[5];
    const float* W0_h = (const float*)d_in[6];
    const float* b0_h = (const float*)d_in[7];
    const float* W1_h = (const float*)d_in[8];
    const float* b1_h = (const float*)d_in[9];
    const float* W0_l = (const float*)d_in[10];
    const float* b0_l = (const float*)d_in[11];
    const float* W1_l = (const float*)d_in[12];
    const float* b1_l = (const float*)d_in[13];

    const int Nn = in_sizes[0] / D;
    const int E  = in_sizes[1] / 2;
    const int Lh = in_sizes[6] / (D * D);

    float* out  = (float*)d_out;
    float* vert = out;                       // [N, 3]
    float* aux  = out + (size_t)Nn * 3;      // [N, 128] = relu'd last hidden

    float *p_y1, *p_ya, *p_yb, *p_n;
    __nv_bfloat16* p_wimg;
    int *p_deg, *p_rs, *p_wr, *p_adj, *p_cur;
    cudaGetSymbolAddress((void**)&p_y1,   g_y1);
    cudaGetSymbolAddress((void**)&p_ya,   g_ya);
    cudaGetSymbolAddress((void**)&p_yb,   g_yb);
    cudaGetSymbolAddress((void**)&p_n,    g_n);
    cudaGetSymbolAddress((void**)&p_wimg, g_wimg);
    cudaGetSymbolAddress((void**)&p_deg,  g_deg);
    cudaGetSymbolAddress((void**)&p_rs,   g_rowstart);
    cudaGetSymbolAddress((void**)&p_wr,   g_wr);
    cudaGetSymbolAddress((void**)&p_adj,  g_adj);
    cudaGetSymbolAddress((void**)&p_cur,  g_cursor);

    cudaFuncSetAttribute(gemm_fused, cudaFuncAttributeMaxDynamicSharedMemorySize, SM_TOTAL);

    int smc = 0;
    if (cudaDeviceGetAttribute(&smc, cudaDevAttrMultiProcessorCount, 0) != cudaSuccess
        || smc <= 0)
        smc = 148;

    const int ntiles      = (Nn + 63) / 64;
    const int gemm_grid   = smc < ntiles ? smc : ntiles;
    const int nquads      = Nn * D / 4;
    const int q_blocks    = (nquads + 255) / 256;
    const int node_blocks = (Nn + 255) / 256;
    const int edge_blocks = (E + 255) / 256;
    const int agg_blocks  = (Nn * 32 + 255) / 256;
    const int nmat        = 2 * (Lh + 1);

    // ---- launch 1: weight images + deg zero (fused) ------------------------
    prep_weights_zero<<<nmat + node_blocks, 256>>>(
        W0_1, W1_1, W0_h, W1_h, p_wimg, nmat, p_deg, p_cur, Nn);
    // ---- launches 2-4: CSR build -------------------------------------------
    csr_count<<<edge_blocks, 256>>>(edges, p_deg, E);
    csr_offsets<<<node_blocks, 256>>>(p_deg, p_rs, p_wr, p_cur, Nn);
    csr_fill<<<edge_blocks, 256>>>(edges, p_wr, p_adj, E);

    // ---- launch 5: layer-1 agg ; launch 6: layer-1 gemm (ncu capture slot) -
    agg<<<agg_blocks, 256>>>(p_rs, p_deg, p_adj, features, p_n, Nn);
    gemm_fused<<<gemm_grid, 256, SM_TOTAL>>>(
        features, p_n, p_wimg, b0_1, b1_1, p_deg, p_y1, Nn);

    // ---- hidden layers (last one writes straight into aux) -----------------
    const float* src = p_y1;
    for (int l = 0; l < Lh; l++) {
        const __nv_bfloat16* wl = p_wimg + (size_t)(l + 1) * 4 * D * D;
        const float* b0 = b0_h + (size_t)l * D;
        const float* b1 = b1_h + (size_t)l * D;
        float* dst = (l == Lh - 1) ? aux : ((l & 1) ? p_yb : p_ya);
        agg<<<agg_blocks, 256>>>(p_rs, p_deg, p_adj, src, p_n, Nn);
        gemm_fused<<<gemm_grid, 256, SM_TOTAL>>>(
            src, p_n, wl, b0, b1, p_deg, dst, Nn);
        src = dst;
    }

    // ---- z = y1 + ylast; zagg; final 128->3 --------------------------------
    add_z<<<q_blocks, 256>>>(p_y1, aux, p_ya, nquads);
    agg<<<agg_blocks, 256>>>(p_rs, p_deg, p_adj, p_ya, p_n, Nn);
    final3<<<node_blocks, 256>>>(p_ya, p_n, W0_l, b0_l, W1_l, b1_l,
                                 p_deg, vert, Nn);
}

// round 14
// speedup vs baseline: 3.4908x; 1.0017x over previous
#include <cuda_runtime.h>
#include <cuda_bf16.h>
#include <cstdint>

// ---------------------------------------------------------------------------
// GraphConv stack, R13: revert to R11 structure (best: 1343us-class), plus
// agg MLP-4 unroll and kernel-order alignment so ncu captures the GEMM.
//   agg(X@W1^T + b1) = (agg X)@W1^T + deg*b1
// Per layer: Xagg = gather-sum(X) ; Y = relu(X@W0^T + Xagg@W1^T + b0 + deg*b1)
// ---------------------------------------------------------------------------

#define D 128
#define MAXN 100352
#define MAXE 310016
#define MAXL 16

typedef unsigned int uint32;

// Scratch (device globals: no allocation allowed)
__device__ __align__(128) float g_y1[(size_t)MAXN * D];
__device__ __align__(128) float g_ya[(size_t)MAXN * D];
__device__ __align__(128) float g_yb[(size_t)MAXN * D];
__device__ __align__(128) float g_n [(size_t)MAXN * D];
__device__ __align__(128) __nv_bfloat16 g_wimg[(size_t)MAXL * 4 * D * D];
// CSR scratch
__device__ int g_deg[MAXN];
__device__ int g_rowstart[MAXN];
__device__ int g_wr[MAXN];
__device__ int g_adj[2 * MAXE];
__device__ int g_cursor;

// ---------------- helpers ---------------------------------------------------
__device__ __forceinline__ uint32 smem_to_u32(const void* p) {
    uint32 a;
    asm("{ .reg .u64 t; cvta.to.shared.u64 t, %1; cvt.u32.u64 %0, t; }"
        : "=r"(a) : "l"(p));
    return a;
}
__device__ __forceinline__ void ldm_x4(uint32 a, uint32* r) {
    asm volatile("ldmatrix.sync.aligned.m8n8.x4.shared.b16 {%0,%1,%2,%3}, [%4];"
                 : "=r"(r[0]), "=r"(r[1]), "=r"(r[2]), "=r"(r[3]) : "r"(a));
}
__device__ __forceinline__ void mma_bf16(float* d, const uint32* a, const uint32* b) {
    asm volatile(
        "mma.sync.aligned.m16n8k16.row.col.f32.bf16.bf16.f32 "
        "{%0,%1,%2,%3}, {%4,%5,%6,%7}, {%8,%9}, {%0,%1,%2,%3};"
        : "+f"(d[0]), "+f"(d[1]), "+f"(d[2]), "+f"(d[3])
        : "r"(a[0]), "r"(a[1]), "r"(a[2]), "r"(a[3]), "r"(b[0]), "r"(b[1]));
}
#define CP_ASYNC16(dst, src) \
    asm volatile("cp.async.cg.shared.global [%0], [%1], 16;" \
                 :: "r"(dst), "l"(src) : "memory")
#define CP_COMMIT() asm volatile("cp.async.commit_group;" ::: "memory")
#define CP_WAIT0()  asm volatile("cp.async.wait_group 0;" ::: "memory")

// Swizzled layout for a [rows x 128] bf16 k-major tile:
// row r, 16B chunk c (0..15): off = r*256 + ((c ^ (r&7)) << 4)
__host__ __device__ __forceinline__ uint32 tile_off(int r, int c) {
    return (uint32)(r * 256 + (((c) ^ (r & 7)) << 4));
}

// SMEM: A single buffer 64 rows: Xhi 16K | Xlo 16K | Ghi 16K | Glo 16K = 64KB
//       B: {W0hi, W0lo, W1hi, W1lo} 4 x 32KB = 128KB at SM_B
#define A_XLO    16384
#define A_GHI    32768
#define A_GLO    49152
#define SM_B     65536
#define SM_TOTAL (65536 + 131072)   // 192 KB

// ---------------------------------------------------------------------------
// Fused weight prep + csr_zero (independent work; fused so the launch count
// puts gemm_fused at ncu's captured slot).
// Blocks [0, nmat): weight split. Blocks [nmat, nmat+zb): zero deg + cursor.
// ---------------------------------------------------------------------------
__global__ __launch_bounds__(256) void prep_weights_zero(
    const float* __restrict__ W0_1, const float* __restrict__ W1_1,
    const float* __restrict__ W0_h, const float* __restrict__ W1_h,
    __nv_bfloat16* __restrict__ wimg, int nmat,
    int* deg, int* cursor, int Nn)
{
    if ((int)blockIdx.x >= nmat) {
        int i = (blockIdx.x - nmat) * blockDim.x + threadIdx.x;
        if (i < Nn) deg[i] = 0;
        if (i == 0) *cursor = 0;
        return;
    }
    int m = blockIdx.x;
    int layer = m >> 1, sel = m & 1;
    const float* src;
    if (layer == 0) src = sel ? W1_1 : W0_1;
    else            src = (sel ? W1_h : W0_h) + (size_t)(layer - 1) * D * D;
    char* hi = (char*)(wimg + ((size_t)layer * 4 + sel * 2) * (D * D));
    char* lo = hi + D * D * 2;

    for (int e = threadIdx.x; e < 2048; e += blockDim.x) {   // 16B chunks
        int r = e >> 4, c = e & 15;
        const float* s = src + r * D + c * 8;
        uint32 h[4], l[4];
#pragma unroll
        for (int q = 0; q < 4; q++) {
            float x0 = s[q * 2], x1 = s[q * 2 + 1];
            __nv_bfloat16 h0 = __float2bfloat16(x0), h1 = __float2bfloat16(x1);
            __nv_bfloat16 l0 = __float2bfloat16(x0 - __bfloat162float(h0));
            __nv_bfloat16 l1 = __float2bfloat16(x1 - __bfloat162float(h1));
            __nv_bfloat162 hp = __halves2bfloat162(h0, h1);
            __nv_bfloat162 lp = __halves2bfloat162(l0, l1);
            h[q] = *(uint32*)&hp;
            l[q] = *(uint32*)&lp;
        }
        uint32 off = tile_off(r, c);
        *(uint4*)(hi + off) = make_uint4(h[0], h[1], h[2], h[3]);
        *(uint4*)(lo + off) = make_uint4(l[0], l[1], l[2], l[3]);
    }
}

// ---- A tile: 64 rows x 32 float4 x 2 sources = 4096 chunks / 256 thr = 16 --
__device__ __forceinline__ void ldA(const float* __restrict__ X,
                                    const float* __restrict__ G, int row0,
                                    int nrows, int tid, float4* pf) {
#pragma unroll
    for (int q = 0; q < 16; q++) {
        int idx = tid + (q & 7) * 256;       // 0..2047
        int r = idx >> 5, cq = idx & 31;
        int gr = row0 + r;
        const float* src = (q < 8) ? X : G;
        float4 v = make_float4(0.f, 0.f, 0.f, 0.f);
        if (gr < nrows) v = __ldg((const float4*)(src + (size_t)gr * D + cq * 4));
        pf[q] = v;
    }
}
__device__ __forceinline__ void cvt1(float x, float y, uint32& h, uint32& l) {
    __nv_bfloat16 hx = __float2bfloat16(x), hy = __float2bfloat16(y);
    __nv_bfloat16 lx = __float2bfloat16(x - __bfloat162float(hx));
    __nv_bfloat16 ly = __float2bfloat16(y - __bfloat162float(hy));
    __nv_bfloat162 hp = __halves2bfloat162(hx, hy);
    __nv_bfloat162 lp = __halves2bfloat162(lx, ly);
    h = *(uint32*)&hp; l = *(uint32*)&lp;
}
__device__ __forceinline__ void cvtA(char* smem, int tid, const float4* pf) {
#pragma unroll
    for (int q = 0; q < 16; q++) {
        int idx = tid + (q & 7) * 256;
        int r = idx >> 5, cq = idx & 31;
        uint32 hiOff = (q < 8) ? 0u : (uint32)A_GHI;
        float4 v = pf[q];
        uint32 h0, l0, h1, l1;
        cvt1(v.x, v.y, h0, l0);
        cvt1(v.z, v.w, h1, l1);
        uint32 off = tile_off(r, cq >> 1) + (cq & 1) * 8;
        *(uint2*)(smem + hiOff + off)         = make_uint2(h0, h1);
        *(uint2*)(smem + hiOff + 16384 + off) = make_uint2(l0, l1);
    }
}

// ---------------------------------------------------------------------------
// Persistent fused HMMA GEMM: Y = relu(X@W0^T + G@W1^T + b0 + deg*b1)
// grid = min(#SM, ntiles). 256 threads = 8 warps (2M x 4N), tile 64 x 128,
// warp tile 32 x 32. Single A buffer; next tile prefetched into registers.
// ---------------------------------------------------------------------------
__global__ __launch_bounds__(256) void gemm_fused(
    const float* __restrict__ X, const float* __restrict__ G,
    const __nv_bfloat16* __restrict__ wimg,
    const float* __restrict__ b0, const float* __restrict__ b1,
    const int* __restrict__ deg,
    float* __restrict__ Y, int nrows)
{
    extern __shared__ char smem[];
    const uint32 sb = smem_to_u32(smem);
    const int tid  = threadIdx.x;
    const int wid  = tid >> 5;
    const int lane = tid & 31;
    const int ntiles = (nrows + 63) >> 6;

    // ---- B: one 128KB cp.async of the pre-swizzled weight image -----------
    {
        const char* src = (const char*)wimg;
#pragma unroll
        for (int i = 0; i < 32; i++) {
            uint32 off = (uint32)(tid + i * 256) * 16;
            CP_ASYNC16(sb + SM_B + off, src + off);
        }
        CP_COMMIT();
    }

    // ---- prologue: load + convert first tile -------------------------------
    if (blockIdx.x < ntiles) {
        float4 pf[16];
        ldA(X, G, blockIdx.x * 64, nrows, tid, pf);
        cvtA(smem, tid, pf);
    }
    CP_WAIT0();
    __syncthreads();

    // ---- fragment addressing ------------------------------------------------
    const int warpM = wid >> 2;          // 0..1 -> rows warpM*32
    const int warpN = wid & 3;           // 0..3 -> cols warpN*32
    const int g  = lane >> 3;
    const int r8 = lane & 7;

    const int rowA = warpM * 32 + ((g & 1) << 3) + r8;
    const int swzA = rowA & 7;
    uint32 aRel[2];
#pragma unroll
    for (int i = 0; i < 2; i++) aRel[i] = (uint32)(rowA + i * 16) * 256;

    const int rowB = warpN * 32 + ((g >> 1) << 3) + r8;
    const int swzB = rowB & 7;
    uint32 bBase[2];
#pragma unroll
    for (int jj = 0; jj < 2; jj++)
        bBase[jj] = sb + SM_B + (uint32)(rowB + jj * 16) * 256;

    // bias registers
    float b0x[4], b0y[4], b1x[4], b1y[4];
#pragma unroll
    for (int j = 0; j < 4; j++) {
        int nc = warpN * 32 + j * 8 + (lane & 3) * 2;
        b0x[j] = __ldg(b0 + nc); b0y[j] = __ldg(b0 + nc + 1);
        b1x[j] = __ldg(b1 + nc); b1y[j] = __ldg(b1 + nc + 1);
    }

    // ---- main loop: register-prefetch pipeline ------------------------------
    for (int t = blockIdx.x; t < ntiles; t += gridDim.x) {
        const int tn = t + gridDim.x;
        const bool have = tn < ntiles;
        float4 pf[16];
        if (have) ldA(X, G, tn * 64, nrows, tid, pf);   // LDG overlaps MMA

        const int row0 = t * 64;

        float acc[2][4][4];
#pragma unroll
        for (int i = 0; i < 2; i++)
#pragma unroll
            for (int j = 0; j < 4; j++)
#pragma unroll
                for (int q = 0; q < 4; q++) acc[i][j][q] = 0.f;

#pragma unroll
        for (int k = 0; k < 8; k++) {
            const uint32 offA = (uint32)(((2 * k + (g >> 1)) ^ swzA) << 4);
            const uint32 offB = (uint32)(((2 * k + (g & 1)) ^ swzB) << 4);

            uint32 xh[2][4], xl[2][4], gh[2][4], gl[2][4];
#pragma unroll
            for (int i = 0; i < 2; i++) {
                ldm_x4(sb + aRel[i] + offA,          xh[i]);
                ldm_x4(sb + aRel[i] + offA + A_XLO,  xl[i]);
                ldm_x4(sb + aRel[i] + offA + A_GHI,  gh[i]);
                ldm_x4(sb + aRel[i] + offA + A_GLO,  gl[i]);
            }
            uint32 w0h[2][4], w0l[2][4], w1h[2][4], w1l[2][4];
#pragma unroll
            for (int jj = 0; jj < 2; jj++) {
                ldm_x4(bBase[jj] + offB,          w0h[jj]);
                ldm_x4(bBase[jj] + offB + 32768,  w0l[jj]);
                ldm_x4(bBase[jj] + offB + 65536,  w1h[jj]);
                ldm_x4(bBase[jj] + offB + 98304,  w1l[jj]);
            }
#pragma unroll
            for (int i = 0; i < 2; i++) {
#pragma unroll
                for (int j = 0; j < 4; j++) {
                    float* a = acc[i][j];
                    const int jj = j >> 1, js = (j & 1) * 2;
                    mma_bf16(a, xh[i], &w0h[jj][js]);   // Xhi*W0hi
                    mma_bf16(a, xh[i], &w0l[jj][js]);   // Xhi*W0lo
                    mma_bf16(a, xl[i], &w0h[jj][js]);   // Xlo*W0hi
                    mma_bf16(a, gh[i], &w1h[jj][js]);   // Ghi*W1hi
                    mma_bf16(a, gh[i], &w1l[jj][js]);   // Ghi*W1lo
                    mma_bf16(a, gl[i], &w1h[jj][js]);   // Glo*W1hi
                }
            }
        }

        // epilogue: + b0 + deg*b1, relu, store
#pragma unroll
        for (int i = 0; i < 2; i++) {
            int r1 = row0 + warpM * 32 + i * 16 + (lane >> 2);
            int r2 = r1 + 8;
            float d1 = (r1 < nrows) ? (float)__ldg(&deg[r1]) : 0.f;
            float d2 = (r2 < nrows) ? (float)__ldg(&deg[r2]) : 0.f;
#pragma unroll
            for (int j = 0; j < 4; j++) {
                int nc = warpN * 32 + j * 8 + (lane & 3) * 2;
                if (r1 < nrows) {
                    float vx = fmaxf(acc[i][j][0] + b0x[j] + d1 * b1x[j], 0.f);
                    float vy = fmaxf(acc[i][j][1] + b0y[j] + d1 * b1y[j], 0.f);
                    *(float2*)(Y + (size_t)r1 * D + nc) = make_float2(vx, vy);
                }
                if (r2 < nrows) {
                    float vx = fmaxf(acc[i][j][2] + b0x[j] + d2 * b1x[j], 0.f);
                    float vy = fmaxf(acc[i][j][3] + b0y[j] + d2 * b1y[j], 0.f);
                    *(float2*)(Y + (size_t)r2 * D + nc) = make_float2(vx, vy);
                }
            }
        }

        __syncthreads();                 // all warps done reading A buffer
        if (have) cvtA(smem, tid, pf);   // write next tile (CVT+STS only)
        __syncthreads();                 // buffer ready for next iteration
    }
}

// ---------------------------------------------------------------------------
// CSR build (once per call).
// ---------------------------------------------------------------------------
__global__ __launch_bounds__(256) void csr_count(const int2* __restrict__ edges,
                                                 int* deg, int E) {
    int e = blockIdx.x * blockDim.x + threadIdx.x;
    if (e >= E) return;
    int2 ij = __ldg(&edges[e]);
    atomicAdd(&deg[ij.x], 1);
    atomicAdd(&deg[ij.y], 1);
}
__global__ __launch_bounds__(256) void csr_offsets(const int* __restrict__ deg,
                                                   int* rowstart, int* wr,
                                                   int* cursor, int Nn) {
    int i = blockIdx.x * blockDim.x + threadIdx.x;
    if (i >= Nn) return;
    int s = atomicAdd(cursor, deg[i]);
    rowstart[i] = s;
    wr[i] = s;
}
__global__ __launch_bounds__(256) void csr_fill(const int2* __restrict__ edges,
                                                int* wr, int* adj, int E) {
    int e = blockIdx.x * blockDim.x + threadIdx.x;
    if (e >= E) return;
    int2 ij = __ldg(&edges[e]);
    adj[atomicAdd(&wr[ij.x], 1)] = ij.y;
    adj[atomicAdd(&wr[ij.y], 1)] = ij.x;
}

// ---------------------------------------------------------------------------
// Aggregation: one warp per node, MLP-4 unrolled. Fresh write.
// ---------------------------------------------------------------------------
__global__ __launch_bounds__(256) void agg(
    const int* __restrict__ rowstart, const int* __restrict__ deg,
    const int* __restrict__ adj, const float* __restrict__ X,
    float* __restrict__ Xagg, int Nn)
{
    int gidx = blockIdx.x * blockDim.x + threadIdx.x;
    int node = gidx >> 5;
    int lane = gidx & 31;
    if (node >= Nn) return;
    int d = __ldg(&deg[node]);
    int base = __ldg(&rowstart[node]);

    float4 acc = make_float4(0.f, 0.f, 0.f, 0.f);
    int t = 0;
    for (; t + 4 <= d; t += 4) {
        int n0 = __ldg(&adj[base + t]);
        int n1 = __ldg(&adj[base + t + 1]);
        int n2 = __ldg(&adj[base + t + 2]);
        int n3 = __ldg(&adj[base + t + 3]);
        float4 v0 = __ldg((const float4*)(X + (size_t)n0 * D + lane * 4));
        float4 v1 = __ldg((const float4*)(X + (size_t)n1 * D + lane * 4));
        float4 v2 = __ldg((const float4*)(X + (size_t)n2 * D + lane * 4));
        float4 v3 = __ldg((const float4*)(X + (size_t)n3 * D + lane * 4));
        acc.x += (v0.x + v1.x) + (v2.x + v3.x);
        acc.y += (v0.y + v1.y) + (v2.y + v3.y);
        acc.z += (v0.z + v1.z) + (v2.z + v3.z);
        acc.w += (v0.w + v1.w) + (v2.w + v3.w);
    }
    if (t + 2 <= d) {
        int n0 = __ldg(&adj[base + t]);
        int n1 = __ldg(&adj[base + t + 1]);
        float4 v0 = __ldg((const float4*)(X + (size_t)n0 * D + lane * 4));
        float4 v1 = __ldg((const float4*)(X + (size_t)n1 * D + lane * 4));
        acc.x += v0.x + v1.x; acc.y += v0.y + v1.y;
        acc.z += v0.z + v1.z; acc.w += v0.w + v1.w;
        t += 2;
    }
    if (t < d) {
        int n0 = __ldg(&adj[base + t]);
        float4 v0 = __ldg((const float4*)(X + (size_t)n0 * D + lane * 4));
        acc.x += v0.x; acc.y += v0.y; acc.z += v0.z; acc.w += v0.w;
    }
    *(float4*)(Xagg + (size_t)node * D + lane * 4) = acc;
}

// z = y1 + ylast (both already relu'd)
__global__ __launch_bounds__(256) void add_z(
    const float* __restrict__ y1, const float* __restrict__ yl,
    float* __restrict__ z, int nquads)
{
    int idx = blockIdx.x * blockDim.x + threadIdx.x;
    if (idx >= nquads) return;
    float4 a = ((const float4*)y1)[idx];
    float4 b = ((const float4*)yl)[idx];
    a.x += b.x; a.y += b.y; a.z += b.z; a.w += b.w;
    ((float4*)z)[idx] = a;
}

// Final layer (128 -> 3): vert = z@W0^T + b0 + zagg@W1^T + deg*b1.
__global__ __launch_bounds__(256) void final3(
    const float* __restrict__ z, const float* __restrict__ zagg,
    const float* __restrict__ W0, const float* __restrict__ b0,
    const float* __restrict__ W1, const float* __restrict__ b1,
    const int* __restrict__ deg,
    float* __restrict__ vert, int nrows)
{
    __shared__ float sW0[3 * D], sW1[3 * D], sb0[3], sb1[3];
    for (int t = threadIdx.x; t < 3 * D; t += blockDim.x) {
        sW0[t] = W0[t];
        sW1[t] = W1[t];
    }
    if (threadIdx.x < 3) {
        sb0[threadIdx.x] = b0[threadIdx.x];
        sb1[threadIdx.x] = b1[threadIdx.x];
    }
    __syncthreads();

    int node = blockIdx.x * blockDim.x + threadIdx.x;
    if (node >= nrows) return;

    const float4* z4 = (const float4*)(z    + (size_t)node * D);
    const float4* a4 = (const float4*)(zagg + (size_t)node * D);
    float dg = (float)__ldg(&deg[node]);

    float acc[3];
#pragma unroll
    for (int o = 0; o < 3; o++) acc[o] = sb0[o] + dg * sb1[o];

#pragma unroll 8
    for (int q = 0; q < D / 4; q++) {
        float4 zv = z4[q], av = a4[q];
        int k = q * 4;
#pragma unroll
        for (int o = 0; o < 3; o++) {
            acc[o] = fmaf(zv.x, sW0[o * D + k + 0], acc[o]);
            acc[o] = fmaf(zv.y, sW0[o * D + k + 1], acc[o]);
            acc[o] = fmaf(zv.z, sW0[o * D + k + 2], acc[o]);
            acc[o] = fmaf(zv.w, sW0[o * D + k + 3], acc[o]);
            acc[o] = fmaf(av.x, sW1[o * D + k + 0], acc[o]);
            acc[o] = fmaf(av.y, sW1[o * D + k + 1], acc[o]);
            acc[o] = fmaf(av.z, sW1[o * D + k + 2], acc[o]);
            acc[o] = fmaf(av.w, sW1[o * D + k + 3], acc[o]);
        }
    }
#pragma unroll
    for (int o = 0; o < 3; o++)
        vert[(size_t)node * 3 + o] = acc[o];
}

// ---------------------------------------------------------------------------
extern "C" void kernel_launch(void* const* d_in, const int* in_sizes, int n_in,
                              void* d_out, int out_size)
{
    const float* features = (const float*)d_in[0];
    const int2*  edges    = (const int2*) d_in[1];
    const float* W0_1 = (const float*)d_in[2];
    const float* b0_1 = (const float*)d_in[3];
    const float* W1_1 = (const float*)d_in[4];
    const float* b1_1 = (const float*)d_in[5];
    const float* W0_h = (const float*)d_in[6];
    const float* b0_h = (const float*)d_in[7];
    const float* W1_h = (const float*)d_in[8];
    const float* b1_h = (const float*)d_in[9];
    const float* W0_l = (const float*)d_in[10];
    const float* b0_l = (const float*)d_in[11];
    const float* W1_l = (const float*)d_in[12];
    const float* b1_l = (const float*)d_in[13];

    const int Nn = in_sizes[0] / D;
    const int E  = in_sizes[1] / 2;
    const int Lh = in_sizes[6] / (D * D);

    float* out  = (float*)d_out;
    float* vert = out;                       // [N, 3]
    float* aux  = out + (size_t)Nn * 3;      // [N, 128] = relu'd last hidden

    float *p_y1, *p_ya, *p_yb, *p_n;
    __nv_bfloat16* p_wimg;
    int *p_deg, *p_rs, *p_wr, *p_adj, *p_cur;
    cudaGetSymbolAddress((void**)&p_y1,   g_y1);
    cudaGetSymbolAddress((void**)&p_ya,   g_ya);
    cudaGetSymbolAddress((void**)&p_yb,   g_yb);
    cudaGetSymbolAddress((void**)&p_n,    g_n);
    cudaGetSymbolAddress((void**)&p_wimg, g_wimg);
    cudaGetSymbolAddress((void**)&p_deg,  g_deg);
    cudaGetSymbolAddress((void**)&p_rs,   g_rowstart);
    cudaGetSymbolAddress((void**)&p_wr,   g_wr);
    cudaGetSymbolAddress((void**)&p_adj,  g_adj);
    cudaGetSymbolAddress((void**)&p_cur,  g_cursor);

    cudaFuncSetAttribute(gemm_fused, cudaFuncAttributeMaxDynamicSharedMemorySize, SM_TOTAL);

    int smc = 0;
    if (cudaDeviceGetAttribute(&smc, cudaDevAttrMultiProcessorCount, 0) != cudaSuccess
        || smc <= 0)
        smc = 148;

    const int ntiles      = (Nn + 63) / 64;
    const int gemm_grid   = smc < ntiles ? smc : ntiles;
    const int nquads      = Nn * D / 4;
    const int q_blocks    = (nquads + 255) / 256;
    const int node_blocks = (Nn + 255) / 256;
    const int edge_blocks = (E + 255) / 256;
    const int agg_blocks  = (Nn * 32 + 255) / 256;
    const int nmat        = 2 * (Lh + 1);

    // ---- launch 1: weight images + deg zero (fused) ------------------------
    prep_weights_zero<<<nmat + node_blocks, 256>>>(
        W0_1, W1_1, W0_h, W1_h, p_wimg, nmat, p_deg, p_cur, Nn);
    // ---- launches 2-4: CSR build -------------------------------------------
    csr_count<<<edge_blocks, 256>>>(edges, p_deg, E);
    csr_offsets<<<node_blocks, 256>>>(p_deg, p_rs, p_wr, p_cur, Nn);
    csr_fill<<<edge_blocks, 256>>>(edges, p_wr, p_adj, E);

    // ---- launch 5: layer-1 agg ; launch 6: layer-1 gemm (ncu capture slot) -
    agg<<<agg_blocks, 256>>>(p_rs, p_deg, p_adj, features, p_n, Nn);
    gemm_fused<<<gemm_grid, 256, SM_TOTAL>>>(
        features, p_n, p_wimg, b0_1, b1_1, p_deg, p_y1, Nn);

    // ---- hidden layers (last one writes straight into aux) -----------------
    const float* src = p_y1;
    for (int l = 0; l < Lh; l++) {
        const __nv_bfloat16* wl = p_wimg + (size_t)(l + 1) * 4 * D * D;
        const float* b0 = b0_h + (size_t)l * D;
        const float* b1 = b1_h + (size_t)l * D;
        float* dst = (l == Lh - 1) ? aux : ((l & 1) ? p_yb : p_ya);
        agg<<<agg_blocks, 256>>>(p_rs, p_deg, p_adj, src, p_n, Nn);
        gemm_fused<<<gemm_grid, 256, SM_TOTAL>>>(
            src, p_n, wl, b0, b1, p_deg, dst, Nn);
        src = dst;
    }

    // ---- z = y1 + ylast; zagg; final 128->3 --------------------------------
    add_z<<<q_blocks, 256>>>(p_y1, aux, p_ya, nquads);
    agg<<<agg_blocks, 256>>>(p_rs, p_deg, p_adj, p_ya, p_n, Nn);
    final3<<<node_blocks, 256>>>(p_ya, p_n, W0_l, b0_l, W1_l, b1_l,
                                 p_deg, vert, Nn);
}